// round 3
// baseline (speedup 1.0000x reference)
#include <cuda_runtime.h>
#include <math.h>

#define Bb 4
#define Ssz 2048
#define Dd 1024
#define Hh 16
#define DH 64
#define NBH (Bb*Hh)          // 64
#define BM2 128
#define BN2 64

// Scratch (allocation-free rule: device globals)
__device__ float g_Q[NBH * Ssz * DH];   // [bh][s][d]
__device__ float g_K[NBH * Ssz * DH];   // [bh][s][d]
__device__ float g_Kmean[NBH * DH];

// ---------------------------------------------------------------------------
// Kernel 1: fused QK projection  C = x @ W^T + b, de-interleaved into g_Q/g_K
// x: [8192, 1024], W: [2048, 1024] (row-major, K-contiguous both) -> "NT" GEMM
// ---------------------------------------------------------------------------
__global__ __launch_bounds__(256, 2) void proj_kernel(const float* __restrict__ x,
                                                      const float* __restrict__ W,
                                                      const float* __restrict__ bias) {
    __shared__ float As[8][128];   // [k][m]
    __shared__ float Bs[8][128];   // [k][n]
    const int m0 = blockIdx.y * 128;
    const int n0 = blockIdx.x * 128;
    const int t  = threadIdx.x;
    const int tx = t & 15, ty = t >> 4;
    const int lr = t >> 1, lk = (t & 1) * 4;

    float acc[8][8];
#pragma unroll
    for (int i = 0; i < 8; i++)
#pragma unroll
        for (int j = 0; j < 8; j++) acc[i][j] = 0.f;

    const float* Ap = x + (m0 + lr) * Dd + lk;
    const float* Bp = W + (n0 + lr) * Dd + lk;

    for (int k0 = 0; k0 < Dd; k0 += 8) {
        float4 av = *(const float4*)(Ap + k0);
        float4 bv = *(const float4*)(Bp + k0);
        __syncthreads();
        As[lk + 0][lr] = av.x; As[lk + 1][lr] = av.y;
        As[lk + 2][lr] = av.z; As[lk + 3][lr] = av.w;
        Bs[lk + 0][lr] = bv.x; Bs[lk + 1][lr] = bv.y;
        Bs[lk + 2][lr] = bv.z; Bs[lk + 3][lr] = bv.w;
        __syncthreads();
#pragma unroll
        for (int k = 0; k < 8; k++) {
            float a[8], bb[8];
            float4 a0 = *(const float4*)&As[k][ty * 4];
            float4 a1 = *(const float4*)&As[k][64 + ty * 4];
            float4 b0 = *(const float4*)&Bs[k][tx * 4];
            float4 b1 = *(const float4*)&Bs[k][64 + tx * 4];
            a[0]=a0.x; a[1]=a0.y; a[2]=a0.z; a[3]=a0.w;
            a[4]=a1.x; a[5]=a1.y; a[6]=a1.z; a[7]=a1.w;
            bb[0]=b0.x; bb[1]=b0.y; bb[2]=b0.z; bb[3]=b0.w;
            bb[4]=b1.x; bb[5]=b1.y; bb[6]=b1.z; bb[7]=b1.w;
#pragma unroll
            for (int i = 0; i < 8; i++)
#pragma unroll
                for (int j = 0; j < 8; j++)
                    acc[i][j] = fmaf(a[i], bb[j], acc[i][j]);
        }
    }

    // Epilogue: route column n -> (q|k)[b][h][s][d]; n = (h*64+d)*2 + c
#pragma unroll
    for (int i = 0; i < 8; i++) {
        int rr = (i < 4) ? (ty * 4 + i) : (64 + ty * 4 + (i - 4));
        int m = m0 + rr;
        int b = m >> 11;          // / 2048
        int s = m & 2047;
#pragma unroll
        for (int j = 0; j < 8; j++) {
            int cc = (j < 4) ? (tx * 4 + j) : (64 + tx * 4 + (j - 4));
            int n = n0 + cc;
            float v = acc[i][j] + bias[n];
            int c  = n & 1;
            int hd = n >> 1;            // h*64 + d
            int h  = hd >> 6;
            int d  = hd & 63;
            int dst = ((b * Hh + h) * Ssz + s) * DH + d;
            if (c == 0) g_Q[dst] = v; else g_K[dst] = v;
        }
    }
}

// ---------------------------------------------------------------------------
// Kernel 2: k_mean[bh][d] = mean over s of g_K[bh][s][d]
// ---------------------------------------------------------------------------
__global__ __launch_bounds__(256) void kmean_kernel() {
    __shared__ float red[256];
    const int bh = blockIdx.x;
    const int t = threadIdx.x;
    const int d = t & 63, part = t >> 6;
    const float* kp = g_K + bh * (Ssz * DH) + d;
    float s = 0.f;
    for (int j = part; j < Ssz; j += 4) s += kp[j * DH];
    red[t] = s;
    __syncthreads();
    if (part == 0) {
        float tot = red[d] + red[64 + d] + red[128 + d] + red[192 + d];
        g_Kmean[bh * DH + d] = tot * (1.0f / Ssz);
    }
}

// ---------------------------------------------------------------------------
// Kernel 3: fused attention.
// Per block: one (b,h) and a 128-row i-tile. Loop j in 64-wide tiles:
//   S = Qs Ks^T ; f = selu(scale*S - mu_row) ; out += f @ V
// mu_row = scale * q_row . k_mean  (algebraic identity for the row mean)
// ---------------------------------------------------------------------------
__global__ __launch_bounds__(256) void attn_kernel(const float* __restrict__ x,
                                                   float* __restrict__ out) {
    extern __shared__ float sm[];
    float* Qs = sm;                    // [64][128]   Qs[k*128 + r]
    float* Ks = Qs + 64 * 128;         // [64][68]    Ks[k*68 + c]
    float* Vs = Ks + 64 * 68;          // [64][64]    Vs[c*64 + d]
    float* Ssm = Vs + 64 * 64;         // [64][128]   Ssm[c*128 + r]
    float* mu = Ssm + 64 * 128;        // [128]
    float* km = mu + 128;              // [64]

    const int blk = blockIdx.x;
    const int bh = blk >> 4;           // 0..63
    const int it = blk & 15;
    const int b = bh >> 4, h = bh & 15;
    const int i0 = it * BM2;
    const int t = threadIdx.x;
    const int tx = t & 15, ty = t >> 4;

    // Load Q tile transposed: g_Q[bh][i0+r][k] -> Qs[k][r]
    {
        const float* qg = g_Q + (bh * Ssz + i0) * DH;
#pragma unroll
        for (int p = 0; p < 8; p++) {
            int idx = p * 256 + t;          // float4 index 0..2047
            int r = idx >> 4;               // 0..127
            int kq = (idx & 15) * 4;        // 0..60
            float4 v = *(const float4*)(qg + r * DH + kq);
            Qs[(kq + 0) * 128 + r] = v.x;
            Qs[(kq + 1) * 128 + r] = v.y;
            Qs[(kq + 2) * 128 + r] = v.z;
            Qs[(kq + 3) * 128 + r] = v.w;
        }
    }
    if (t < 64) km[t] = g_Kmean[bh * DH + t];
    __syncthreads();

    if (t < 128) {
        float s = 0.f;
#pragma unroll
        for (int k = 0; k < 64; k++) s = fmaf(Qs[k * 128 + t], km[k], s);
        mu[t] = s * 0.125f;                // scale = dh^-0.5 = 0.125
    }
    __syncthreads();

    float oacc[8][4];
#pragma unroll
    for (int i = 0; i < 8; i++)
#pragma unroll
        for (int j = 0; j < 4; j++) oacc[i][j] = 0.f;

    const float* xg = x + (b * Ssz) * Dd + h * DH;    // V[j][d] = xg[j*Dd + d]
    const float* kg = g_K + bh * (Ssz * DH);

    const float lam = 1.0507009873554805f;
    const float lam_al = 1.0507009873554805f * 1.6732632423543772f;

    for (int j0 = 0; j0 < Ssz; j0 += BN2) {
        __syncthreads();   // protect Ks/Vs/Ssm rewrite vs previous iter's readers
        // Load K (transposed) and V tiles: 64x64 each
#pragma unroll
        for (int p = 0; p < 4; p++) {
            int idx = p * 256 + t;          // float4 index 0..1023
            int c = idx >> 4;               // 0..63
            int kq = (idx & 15) * 4;
            float4 kv = *(const float4*)(kg + (j0 + c) * DH + kq);
            Ks[(kq + 0) * 68 + c] = kv.x;
            Ks[(kq + 1) * 68 + c] = kv.y;
            Ks[(kq + 2) * 68 + c] = kv.z;
            Ks[(kq + 3) * 68 + c] = kv.w;
            float4 vv = *(const float4*)(xg + (j0 + c) * Dd + kq);
            *(float4*)&Vs[c * 64 + kq] = vv;
        }
        __syncthreads();

        // S-compute: thread owns rows {tx*4+i, 64+tx*4+i}, cols {ty*4+j}
        float sv[8][4];
#pragma unroll
        for (int i = 0; i < 8; i++)
#pragma unroll
            for (int j = 0; j < 4; j++) sv[i][j] = 0.f;
#pragma unroll
        for (int k = 0; k < 64; k++) {
            float4 q0 = *(const float4*)&Qs[k * 128 + tx * 4];
            float4 q1 = *(const float4*)&Qs[k * 128 + 64 + tx * 4];
            float4 kk = *(const float4*)&Ks[k * 68 + ty * 4];
            float qa[8] = {q0.x, q0.y, q0.z, q0.w, q1.x, q1.y, q1.z, q1.w};
            float kb[4] = {kk.x, kk.y, kk.z, kk.w};
#pragma unroll
            for (int i = 0; i < 8; i++)
#pragma unroll
                for (int j = 0; j < 4; j++)
                    sv[i][j] = fmaf(qa[i], kb[j], sv[i][j]);
        }
        // selu(scale*s - mu)
#pragma unroll
        for (int i = 0; i < 8; i++) {
            int r = (i < 4) ? (tx * 4 + i) : (64 + tx * 4 + (i - 4));
            float m_ = mu[r];
#pragma unroll
            for (int j = 0; j < 4; j++) {
                float z = fmaf(sv[i][j], 0.125f, -m_);
                sv[i][j] = (z > 0.f) ? (lam * z) : (lam_al * (expf(z) - 1.f));
            }
        }
        // Write S tile (column-major over rows, vectorized along r)
#pragma unroll
        for (int j = 0; j < 4; j++) {
            int c = ty * 4 + j;
            *(float4*)&Ssm[c * 128 + tx * 4] =
                make_float4(sv[0][j], sv[1][j], sv[2][j], sv[3][j]);
            *(float4*)&Ssm[c * 128 + 64 + tx * 4] =
                make_float4(sv[4][j], sv[5][j], sv[6][j], sv[7][j]);
        }
        __syncthreads();

        // GEMM2: out[r][d] += S[r][c] * V[c][d]; rows {ty*4+i, 64+ty*4+i}, d {tx*4+j}
#pragma unroll
        for (int c = 0; c < 64; c++) {
            float4 s0 = *(const float4*)&Ssm[c * 128 + ty * 4];
            float4 s1 = *(const float4*)&Ssm[c * 128 + 64 + ty * 4];
            float4 vv = *(const float4*)&Vs[c * 64 + tx * 4];
            float sa[8] = {s0.x, s0.y, s0.z, s0.w, s1.x, s1.y, s1.z, s1.w};
            float vb[4] = {vv.x, vv.y, vv.z, vv.w};
#pragma unroll
            for (int i = 0; i < 8; i++)
#pragma unroll
                for (int j = 0; j < 4; j++)
                    oacc[i][j] = fmaf(sa[i], vb[j], oacc[i][j]);
        }
    }

    // Epilogue: out[b][i0+r][h*64 + d] = oacc * S^-0.5
    const float os = 0.022097086912079608f;   // 1/sqrt(2048)
    float* og = out + (b * Ssz + i0) * Dd + h * DH;
#pragma unroll
    for (int i = 0; i < 8; i++) {
        int r = (i < 4) ? (ty * 4 + i) : (64 + ty * 4 + (i - 4));
        float4 v = make_float4(oacc[i][0] * os, oacc[i][1] * os,
                               oacc[i][2] * os, oacc[i][3] * os);
        *(float4*)(og + r * Dd + tx * 4) = v;
    }
}

// ---------------------------------------------------------------------------
extern "C" void kernel_launch(void* const* d_in, const int* in_sizes, int n_in,
                              void* d_out, int out_size) {
    const float* x    = (const float*)d_in[0];
    const float* W    = (const float*)d_in[1];
    const float* bias = (const float*)d_in[2];
    float* out = (float*)d_out;

    const int ATTN_SMEM = (64 * 128 + 64 * 68 + 64 * 64 + 64 * 128 + 128 + 64) *
                          (int)sizeof(float);   // 100096 B
    cudaFuncSetAttribute(attn_kernel, cudaFuncAttributeMaxDynamicSharedMemorySize,
                         ATTN_SMEM);

    proj_kernel<<<dim3(16, 64), 256>>>(x, W, bias);
    kmean_kernel<<<NBH, 256>>>();
    attn_kernel<<<NBH * (Ssz / BM2), 256, ATTN_SMEM>>>(x, out);
}